// round 1
// baseline (speedup 1.0000x reference)
#include <cuda_runtime.h>
#include <math.h>

#define NNODES 50000
#define NEDGES 800000
#define NAUG   (NEDGES + NNODES)   // edges + self loops
#define HIDDEN 256

// ---------------- scratch (device globals; no allocation allowed) ----------------
__device__ float g_x   [(size_t)NNODES * 512];   // concat [x_proj | edge_proj]
__device__ float g_xh  [(size_t)NNODES * 256];   // per-layer head features
__device__ float g_acc [(size_t)NNODES * 256];   // GAT aggregation accumulator
__device__ float g_x2  [(size_t)NNODES * 256];   // layer output
__device__ float g_ne  [(size_t)NNODES * 16];    // edge_attr sums
__device__ float g_cnt [NNODES];                 // edge counts
__device__ float g_asrc[NNODES * 4];
__device__ float g_adst[NNODES * 4];
__device__ float g_max [NNODES * 4];
__device__ float g_den [NNODES * 4];
__device__ float g_log [(size_t)NAUG * 4];
__device__ float g_ex  [(size_t)NAUG * 4];

// ---------------- helpers ----------------
__device__ __forceinline__ void atomicMaxF(float* a, float v) {
    // valid for mixed signs with -inf init
    if (v >= 0.f) atomicMax((int*)a, __float_as_int(v));
    else          atomicMin((unsigned int*)a, __float_as_uint(v));
}
__device__ __forceinline__ float lrelu(float x) { return x > 0.f ? x : 0.2f * x; }

// ---------------- generic zero ----------------
__global__ void zero_kernel(float* p, size_t n) {
    size_t i = (size_t)blockIdx.x * blockDim.x + threadIdx.x;
    if (i < n) p[i] = 0.f;
}

// ---------------- SGEMM: C[M,256] = A[M,K] @ B[K,256] (+bias), ldc/cofs for packing ----------------
#define BM 128
#define BN 128
#define BK 8
#define TM 8
#define TN 8
__global__ __launch_bounds__(256) void sgemm_bias(
    const float* __restrict__ A, const float* __restrict__ B,
    const float* __restrict__ bias, float* __restrict__ C,
    int M, int N, int K, int lda, int ldc, int cofs)
{
    __shared__ float As[BK][BM];
    __shared__ float Bs[BK][BN];
    int tid  = threadIdx.x;
    int brow = blockIdx.y, bcol = blockIdx.x;
    int trow = (tid / 16) * TM;
    int tcol = (tid % 16) * TN;
    int arow = tid >> 1;
    int acol = (tid & 1) * 4;
    int browi = tid >> 5;
    int bcoli = (tid & 31) * 4;

    const float* Ablk = A + (size_t)(brow * BM) * lda;
    const float* Bblk = B + bcol * BN;
    float acc[TM][TN] = {};
    int grow_a = brow * BM + arow;

    for (int k0 = 0; k0 < K; k0 += BK) {
        float4 av = make_float4(0.f, 0.f, 0.f, 0.f);
        if (grow_a < M)
            av = *(const float4*)(Ablk + (size_t)arow * lda + k0 + acol);
        As[acol + 0][arow] = av.x;
        As[acol + 1][arow] = av.y;
        As[acol + 2][arow] = av.z;
        As[acol + 3][arow] = av.w;
        float4 bv = *(const float4*)(Bblk + (size_t)(k0 + browi) * N + bcoli);
        *(float4*)&Bs[browi][bcoli] = bv;
        __syncthreads();
        #pragma unroll
        for (int kk = 0; kk < BK; kk++) {
            float ra[TM], rb[TN];
            #pragma unroll
            for (int i = 0; i < TM; i++) ra[i] = As[kk][trow + i];
            #pragma unroll
            for (int j = 0; j < TN; j++) rb[j] = Bs[kk][tcol + j];
            #pragma unroll
            for (int i = 0; i < TM; i++)
                #pragma unroll
                for (int j = 0; j < TN; j++) acc[i][j] += ra[i] * rb[j];
        }
        __syncthreads();
    }
    #pragma unroll
    for (int i = 0; i < TM; i++) {
        int gr = brow * BM + trow + i;
        if (gr >= M) break;
        float* crow = C + (size_t)gr * ldc + cofs + bcol * BN + tcol;
        #pragma unroll
        for (int j = 0; j < TN; j += 4) {
            float4 v;
            int gc = bcol * BN + tcol + j;
            float b0 = bias ? bias[gc + 0] : 0.f;
            float b1 = bias ? bias[gc + 1] : 0.f;
            float b2 = bias ? bias[gc + 2] : 0.f;
            float b3 = bias ? bias[gc + 3] : 0.f;
            v.x = acc[i][j + 0] + b0;
            v.y = acc[i][j + 1] + b1;
            v.z = acc[i][j + 2] + b2;
            v.w = acc[i][j + 3] + b3;
            *(float4*)(crow + j) = v;
        }
    }
}

// ---------------- scatter mean of edge_attr over dst ----------------
__global__ void edge_mean_kernel(const float* __restrict__ ea, const int* __restrict__ ei) {
    int i = blockIdx.x * blockDim.x + threadIdx.x;
    if (i >= NEDGES * 16) return;
    int e = i >> 4, k = i & 15;
    int d = ei[NEDGES + e];
    atomicAdd(&g_ne[(size_t)d * 16 + k], ea[i]);
    if (k == 0) atomicAdd(&g_cnt[d], 1.f);
}

// ---------------- nef = (sum/cnt) @ Wep + bep -> g_x[:,256:512] ----------------
__global__ __launch_bounds__(256) void nef_kernel(const float* __restrict__ Wep,
                                                  const float* __restrict__ bep) {
    __shared__ float s[16];
    int node = blockIdx.x;
    if (threadIdx.x < 16) {
        float c = g_cnt[node];
        c = c < 1.f ? 1.f : c;
        s[threadIdx.x] = g_ne[(size_t)node * 16 + threadIdx.x] / c;
    }
    __syncthreads();
    int c = threadIdx.x;
    float acc = bep[c];
    #pragma unroll
    for (int k = 0; k < 16; k++) acc += s[k] * Wep[k * 256 + c];
    g_x[(size_t)node * 512 + 256 + c] = acc;
}

// ---------------- per-node attention coefficients + init max/den ----------------
__global__ void att_kernel(const float* __restrict__ as, const float* __restrict__ ad) {
    int w = (blockIdx.x * blockDim.x + threadIdx.x) >> 5;
    int lane = threadIdx.x & 31;
    if (w >= NNODES * 4) return;
    int node = w >> 2, h = w & 3;
    const float* xr = g_xh + (size_t)node * 256 + h * 64;
    float s1 = xr[lane] * as[h * 64 + lane] + xr[lane + 32] * as[h * 64 + lane + 32];
    float s2 = xr[lane] * ad[h * 64 + lane] + xr[lane + 32] * ad[h * 64 + lane + 32];
    #pragma unroll
    for (int o = 16; o; o >>= 1) {
        s1 += __shfl_down_sync(0xffffffffu, s1, o);
        s2 += __shfl_down_sync(0xffffffffu, s2, o);
    }
    if (lane == 0) {
        g_asrc[w] = s1;
        g_adst[w] = s2;
        g_max[w] = -INFINITY;
        g_den[w] = 0.f;
    }
}

// ---------------- logits + segment max ----------------
__global__ void logits_max_kernel(const int* __restrict__ ei) {
    int e = blockIdx.x * blockDim.x + threadIdx.x;
    if (e >= NAUG) return;
    int s, d;
    if (e < NEDGES) { s = ei[e]; d = ei[NEDGES + e]; }
    else            { s = d = e - NEDGES; }
    float4 a = *(const float4*)(g_asrc + s * 4);
    float4 b = *(const float4*)(g_adst + d * 4);
    float4 l;
    l.x = lrelu(a.x + b.x);
    l.y = lrelu(a.y + b.y);
    l.z = lrelu(a.z + b.z);
    l.w = lrelu(a.w + b.w);
    *(float4*)(g_log + (size_t)e * 4) = l;
    atomicMaxF(&g_max[d * 4 + 0], l.x);
    atomicMaxF(&g_max[d * 4 + 1], l.y);
    atomicMaxF(&g_max[d * 4 + 2], l.z);
    atomicMaxF(&g_max[d * 4 + 3], l.w);
}

// ---------------- exp + segment sum ----------------
__global__ void exp_sum_kernel(const int* __restrict__ ei) {
    int e = blockIdx.x * blockDim.x + threadIdx.x;
    if (e >= NAUG) return;
    int d = (e < NEDGES) ? ei[NEDGES + e] : e - NEDGES;
    float4 l = *(const float4*)(g_log + (size_t)e * 4);
    float4 m = *(const float4*)(g_max + d * 4);
    float4 v;
    v.x = expf(l.x - m.x);
    v.y = expf(l.y - m.y);
    v.z = expf(l.z - m.z);
    v.w = expf(l.w - m.w);
    *(float4*)(g_ex + (size_t)e * 4) = v;
    atomicAdd(&g_den[d * 4 + 0], v.x);
    atomicAdd(&g_den[d * 4 + 1], v.y);
    atomicAdd(&g_den[d * 4 + 2], v.z);
    atomicAdd(&g_den[d * 4 + 3], v.w);
}

// ---------------- weighted message scatter (warp per edge) ----------------
__global__ void message_kernel(const int* __restrict__ ei) {
    int gw = (blockIdx.x * blockDim.x + threadIdx.x) >> 5;
    int lane = threadIdx.x & 31;
    if (gw >= NAUG) return;
    int s, d;
    if (gw < NEDGES) { s = ei[gw]; d = ei[NEDGES + gw]; }
    else             { s = d = gw - NEDGES; }
    float a4 = 0.f;
    if (lane < 4) a4 = g_ex[(size_t)gw * 4 + lane] / g_den[d * 4 + lane];
    const float* xs = g_xh + (size_t)s * 256;
    float* od = g_acc + (size_t)d * 256;
    #pragma unroll
    for (int j = 0; j < 8; j++) {
        int idx = j * 32 + lane;
        float alpha = __shfl_sync(0xffffffffu, a4, idx >> 6);
        atomicAdd(od + idx, xs[idx] * alpha);
    }
}

// ---------------- bias + ELU ----------------
__global__ void finalize_kernel(const float* __restrict__ bias, float* __restrict__ out) {
    size_t i = (size_t)blockIdx.x * blockDim.x + threadIdx.x;
    if (i >= (size_t)NNODES * 256) return;
    float v = g_acc[i] + bias[(int)(i & 255)];
    out[i] = v > 0.f ? v : expm1f(v);
}

// ---------------- host launch ----------------
static void gat_layer(const float* x, int Kin, const float* W, const float* as,
                      const float* ad, const float* bias, const int* ei,
                      float* pxh, float* pacc, float* xout) {
    dim3 gg(2, (NNODES + BM - 1) / BM);
    sgemm_bias<<<gg, 256>>>(x, W, nullptr, pxh, NNODES, 256, Kin, Kin, 256, 0);
    att_kernel<<<(NNODES * 4 * 32 + 255) / 256, 256>>>(as, ad);
    logits_max_kernel<<<(NAUG + 255) / 256, 256>>>(ei);
    exp_sum_kernel<<<(NAUG + 255) / 256, 256>>>(ei);
    zero_kernel<<<((size_t)NNODES * 256 + 255) / 256, 256>>>(pacc, (size_t)NNODES * 256);
    message_kernel<<<((size_t)NAUG * 32 + 255) / 256, 256>>>(ei);
    finalize_kernel<<<((size_t)NNODES * 256 + 255) / 256, 256>>>(bias, xout);
}

extern "C" void kernel_launch(void* const* d_in, const int* in_sizes, int n_in,
                              void* d_out, int out_size) {
    const float* node_feats = (const float*)d_in[0];
    const float* edge_attr  = (const float*)d_in[1];
    const float* Wnp = (const float*)d_in[2];
    const float* bnp = (const float*)d_in[3];
    const float* Wep = (const float*)d_in[4];
    const float* bep = (const float*)d_in[5];
    const float* Wg1 = (const float*)d_in[6];
    const float* as1 = (const float*)d_in[7];
    const float* ad1 = (const float*)d_in[8];
    const float* bg1 = (const float*)d_in[9];
    const float* Wg2 = (const float*)d_in[10];
    const float* as2 = (const float*)d_in[11];
    const float* ad2 = (const float*)d_in[12];
    const float* bg2 = (const float*)d_in[13];
    const float* Wo  = (const float*)d_in[14];
    const float* bo  = (const float*)d_in[15];
    const int*   ei  = (const int*)d_in[16];   // [2,E] int32 (JAX demotes int64)
    float* out = (float*)d_out;

    float *px, *pxh, *pacc, *px2, *pne, *pcnt;
    cudaGetSymbolAddress((void**)&px,   g_x);
    cudaGetSymbolAddress((void**)&pxh,  g_xh);
    cudaGetSymbolAddress((void**)&pacc, g_acc);
    cudaGetSymbolAddress((void**)&px2,  g_x2);
    cudaGetSymbolAddress((void**)&pne,  g_ne);
    cudaGetSymbolAddress((void**)&pcnt, g_cnt);

    dim3 gg(2, (NNODES + BM - 1) / BM);

    // 1. node projection -> g_x[:, 0:256]
    sgemm_bias<<<gg, 256>>>(node_feats, Wnp, bnp, px, NNODES, 256, 128, 128, 512, 0);

    // 2. edge aggregation (scatter mean) + edge projection -> g_x[:, 256:512]
    zero_kernel<<<((size_t)NNODES * 16 + 255) / 256, 256>>>(pne, (size_t)NNODES * 16);
    zero_kernel<<<(NNODES + 255) / 256, 256>>>(pcnt, NNODES);
    edge_mean_kernel<<<(NEDGES * 16 + 255) / 256, 256>>>(edge_attr, ei);
    nef_kernel<<<NNODES, 256>>>(Wep, bep);

    // 3. GAT layer 1: [N,512] -> [N,256] (+ELU)
    gat_layer(px, 512, Wg1, as1, ad1, bg1, ei, pxh, pacc, px2);

    // 4. GAT layer 2: [N,256] -> [N,256] (+ELU), in-place output over g_x2
    gat_layer(px2, 256, Wg2, as2, ad2, bg2, ei, pxh, pacc, px2);

    // 5. output projection -> d_out
    sgemm_bias<<<gg, 256>>>(px2, Wo, bo, out, NNODES, 256, 256, 256, 256, 0);
}

// round 2
// speedup vs baseline: 1.2046x; 1.2046x over previous
#include <cuda_runtime.h>
#include <math.h>

#define NNODES 50000
#define NEDGES 800000
#define NAUG   (NEDGES + NNODES)   // edges + self loops

// ---------------- scratch (device globals; no allocation allowed) ----------------
__device__ float g_x   [(size_t)NNODES * 512];   // concat [x_proj | edge_proj]
__device__ float g_xh  [(size_t)NNODES * 256];   // per-layer head features
__device__ float g_x2  [(size_t)NNODES * 256];   // layer output
__device__ float g_ne  [(size_t)NNODES * 16];    // edge_attr sums
__device__ float g_cnt [NNODES];                 // edge counts
__device__ float g_asrc[NNODES * 4];
__device__ float g_adst[NNODES * 4];
__device__ int   g_deg   [NNODES];
__device__ int   g_rowptr[NNODES + 1];
__device__ int   g_cursor[NNODES];
__device__ int   g_einc  [NAUG];                 // src node per incoming edge (CSR)

// ---------------- helpers ----------------
__device__ __forceinline__ float lrelu(float x) { return x > 0.f ? x : 0.2f * x; }

__device__ __forceinline__ void ffma2(unsigned long long& d, unsigned long long a,
                                      unsigned long long b) {
    asm("fma.rn.f32x2 %0, %1, %2, %0;" : "+l"(d) : "l"(a), "l"(b));
}
__device__ __forceinline__ unsigned long long pack2(float lo, float hi) {
    unsigned long long v;
    asm("mov.b64 %0, {%1, %2};" : "=l"(v) : "r"(__float_as_uint(lo)), "r"(__float_as_uint(hi)));
    return v;
}
__device__ __forceinline__ void unpack2(unsigned long long v, float& lo, float& hi) {
    unsigned int a, b;
    asm("mov.b64 {%0, %1}, %2;" : "=r"(a), "=r"(b) : "l"(v));
    lo = __uint_as_float(a); hi = __uint_as_float(b);
}

// ---------------- generic zero ----------------
__global__ void zero_kernel(float* p, size_t n) {
    size_t i = (size_t)blockIdx.x * blockDim.x + threadIdx.x;
    if (i < n) p[i] = 0.f;
}

// ---------------- SGEMM via packed f32x2: C[M,N] = A[M,K] @ B[K,N] (+bias) ----------------
#define BM 128
#define BN 128
#define BK 16
#define TM 8
#define TN 8
__global__ __launch_bounds__(256) void sgemm_bias(
    const float* __restrict__ A, const float* __restrict__ B,
    const float* __restrict__ bias, float* __restrict__ C,
    int M, int N, int K, int lda, int ldc, int cofs)
{
    __shared__ float As[BK][BM];
    __shared__ float Bs[BK][BN];
    int tid  = threadIdx.x;
    int brow = blockIdx.y, bcol = blockIdx.x;
    int trow = (tid / 16) * TM;
    int tcol = (tid % 16) * TN;
    int arow = tid >> 1;
    int acol = (tid & 1) * 8;
    int browi = tid >> 5;            // 0..7 (and +8)
    int bcoli = (tid & 31) * 4;

    const float* Ablk = A + (size_t)(brow * BM) * lda;
    const float* Bblk = B + bcol * BN;
    unsigned long long acc2[TM][TN / 2] = {};
    int grow_a = brow * BM + arow;

    for (int k0 = 0; k0 < K; k0 += BK) {
        #pragma unroll
        for (int c = 0; c < 2; c++) {
            float4 av = make_float4(0.f, 0.f, 0.f, 0.f);
            if (grow_a < M)
                av = *(const float4*)(Ablk + (size_t)arow * lda + k0 + acol + c * 4);
            As[acol + c * 4 + 0][arow] = av.x;
            As[acol + c * 4 + 1][arow] = av.y;
            As[acol + c * 4 + 2][arow] = av.z;
            As[acol + c * 4 + 3][arow] = av.w;
        }
        #pragma unroll
        for (int c = 0; c < 2; c++) {
            float4 bv = *(const float4*)(Bblk + (size_t)(k0 + browi + c * 8) * N + bcoli);
            *(float4*)&Bs[browi + c * 8][bcoli] = bv;
        }
        __syncthreads();
        #pragma unroll
        for (int kk = 0; kk < BK; kk++) {
            float ra[TM];
            unsigned long long rb2[TN / 2];
            #pragma unroll
            for (int i = 0; i < TM; i++) ra[i] = As[kk][trow + i];
            #pragma unroll
            for (int j = 0; j < TN / 2; j++)
                rb2[j] = *(const unsigned long long*)&Bs[kk][tcol + j * 2];
            #pragma unroll
            for (int i = 0; i < TM; i++) {
                unsigned long long a2 = pack2(ra[i], ra[i]);
                #pragma unroll
                for (int j = 0; j < TN / 2; j++) ffma2(acc2[i][j], a2, rb2[j]);
            }
        }
        __syncthreads();
    }
    #pragma unroll
    for (int i = 0; i < TM; i++) {
        int gr = brow * BM + trow + i;
        if (gr >= M) break;
        float accf[TN];
        #pragma unroll
        for (int j = 0; j < TN / 2; j++) unpack2(acc2[i][j], accf[2 * j], accf[2 * j + 1]);
        float* crow = C + (size_t)gr * ldc + cofs + bcol * BN + tcol;
        #pragma unroll
        for (int j = 0; j < TN; j += 4) {
            int gc = bcol * BN + tcol + j;
            float4 v;
            v.x = accf[j + 0] + (bias ? bias[gc + 0] : 0.f);
            v.y = accf[j + 1] + (bias ? bias[gc + 1] : 0.f);
            v.z = accf[j + 2] + (bias ? bias[gc + 2] : 0.f);
            v.w = accf[j + 3] + (bias ? bias[gc + 3] : 0.f);
            *(float4*)(crow + j) = v;
        }
    }
}

// ---------------- scatter mean of edge_attr over dst ----------------
__global__ void edge_mean_kernel(const float* __restrict__ ea, const int* __restrict__ ei) {
    int i = blockIdx.x * blockDim.x + threadIdx.x;
    if (i >= NEDGES * 16) return;
    int e = i >> 4, k = i & 15;
    int d = ei[NEDGES + e];
    atomicAdd(&g_ne[(size_t)d * 16 + k], ea[i]);
    if (k == 0) atomicAdd(&g_cnt[d], 1.f);
}

// ---------------- nef = (sum/cnt) @ Wep + bep -> g_x[:,256:512] ----------------
__global__ __launch_bounds__(256) void nef_kernel(const float* __restrict__ Wep,
                                                  const float* __restrict__ bep) {
    __shared__ float s[16];
    int node = blockIdx.x;
    if (threadIdx.x < 16) {
        float c = g_cnt[node];
        c = c < 1.f ? 1.f : c;
        s[threadIdx.x] = g_ne[(size_t)node * 16 + threadIdx.x] / c;
    }
    __syncthreads();
    int c = threadIdx.x;
    float acc = bep[c];
    #pragma unroll
    for (int k = 0; k < 16; k++) acc += s[k] * Wep[k * 256 + c];
    g_x[(size_t)node * 512 + 256 + c] = acc;
}

// ---------------- CSR build ----------------
__global__ void hist_kernel(const int* __restrict__ ei) {
    int e = blockIdx.x * blockDim.x + threadIdx.x;
    if (e >= NAUG) return;
    int d = (e < NEDGES) ? ei[NEDGES + e] : e - NEDGES;
    atomicAdd(&g_deg[d], 1);
}

#define SCAN_T 1024
__global__ __launch_bounds__(SCAN_T) void scan_kernel() {
    __shared__ int part[SCAN_T];
    int t = threadIdx.x;
    const int CH = (NNODES + SCAN_T - 1) / SCAN_T;
    int base = t * CH;
    int sum = 0;
    for (int i = 0; i < CH; i++) {
        int idx = base + i;
        if (idx < NNODES) sum += g_deg[idx];
    }
    part[t] = sum;
    __syncthreads();
    for (int off = 1; off < SCAN_T; off <<= 1) {
        int v = (t >= off) ? part[t - off] : 0;
        __syncthreads();
        part[t] += v;
        __syncthreads();
    }
    int run = part[t] - sum;   // exclusive prefix
    for (int i = 0; i < CH; i++) {
        int idx = base + i;
        if (idx < NNODES) {
            g_rowptr[idx] = run;
            g_cursor[idx] = run;
            run += g_deg[idx];
        }
    }
    if (t == SCAN_T - 1) g_rowptr[NNODES] = NAUG;
}

__global__ void scatter_kernel(const int* __restrict__ ei) {
    int e = blockIdx.x * blockDim.x + threadIdx.x;
    if (e >= NAUG) return;
    int s, d;
    if (e < NEDGES) { s = ei[e]; d = ei[NEDGES + e]; }
    else            { s = d = e - NEDGES; }
    int pos = atomicAdd(&g_cursor[d], 1);
    g_einc[pos] = s;
}

// ---------------- per-node attention coefficients ----------------
__global__ void att_kernel(const float* __restrict__ as, const float* __restrict__ ad) {
    int w = (blockIdx.x * blockDim.x + threadIdx.x) >> 5;
    int lane = threadIdx.x & 31;
    if (w >= NNODES * 4) return;
    int node = w >> 2, h = w & 3;
    const float* xr = g_xh + (size_t)node * 256 + h * 64;
    float s1 = xr[lane] * as[h * 64 + lane] + xr[lane + 32] * as[h * 64 + lane + 32];
    float s2 = xr[lane] * ad[h * 64 + lane] + xr[lane + 32] * ad[h * 64 + lane + 32];
    #pragma unroll
    for (int o = 16; o; o >>= 1) {
        s1 += __shfl_down_sync(0xffffffffu, s1, o);
        s2 += __shfl_down_sync(0xffffffffu, s2, o);
    }
    if (lane == 0) {
        g_asrc[w] = s1;
        g_adst[w] = s2;
    }
}

// ---------------- fused GAT: online softmax + gather-aggregate + bias + ELU ----------------
__global__ __launch_bounds__(256) void gat_fused(const float* __restrict__ bias,
                                                 float* __restrict__ out) {
    __shared__ float sm[256];
    __shared__ float sd[256];
    int node = blockIdx.x;
    int tid = threadIdx.x;
    int beg = g_rowptr[node], end = g_rowptr[node + 1];
    int deg = end - beg;

    // Phase 1: online softmax stats. thread = (lane e-slot, head)
    int h = tid & 3;
    int es = tid >> 2;                 // 0..63
    float adst = g_adst[node * 4 + h];
    float m = -INFINITY, dsum = 0.f;
    for (int i = es; i < deg; i += 64) {
        int s = g_einc[beg + i];
        float l = lrelu(g_asrc[s * 4 + h] + adst);
        if (l > m) { dsum = dsum * __expf(m - l) + 1.f; m = l; }
        else       { dsum += __expf(l - m); }
    }
    sm[tid] = m; sd[tid] = dsum;
    __syncthreads();
    #pragma unroll
    for (int s = 32; s >= 1; s >>= 1) {
        if (es < s) {
            float m1 = sm[tid], d1 = sd[tid];
            float m2 = sm[tid + 4 * s], d2 = sd[tid + 4 * s];
            float M = fmaxf(m1, m2);
            float e1 = (m1 == -INFINITY) ? 0.f : __expf(m1 - M);
            float e2 = (m2 == -INFINITY) ? 0.f : __expf(m2 - M);
            sm[tid] = M;
            sd[tid] = d1 * e1 + d2 * e2;
        }
        __syncthreads();
    }

    // Phase 2: aggregate. thread = feature; head = tid>>6
    int h2 = tid >> 6;
    float M = sm[h2];
    float Dinv = 1.f / sd[h2];
    float adst2 = g_adst[node * 4 + h2];
    float acc = 0.f;
    for (int e = beg; e < end; e++) {
        int s = g_einc[e];
        float l = lrelu(g_asrc[s * 4 + h2] + adst2);
        float alpha = __expf(l - M) * Dinv;
        acc += alpha * g_xh[(size_t)s * 256 + tid];
    }
    float v = acc + bias[tid];
    out[(size_t)node * 256 + tid] = v > 0.f ? v : expm1f(v);
}

// ---------------- host launch ----------------
static void gat_layer(const float* x, int Kin, const float* W, const float* as,
                      const float* ad, const float* bias, float* pxh, float* xout) {
    dim3 gg(2, (NNODES + BM - 1) / BM);
    sgemm_bias<<<gg, 256>>>(x, W, nullptr, pxh, NNODES, 256, Kin, Kin, 256, 0);
    att_kernel<<<(NNODES * 4 * 32 + 255) / 256, 256>>>(as, ad);
    gat_fused<<<NNODES, 256>>>(bias, xout);
}

extern "C" void kernel_launch(void* const* d_in, const int* in_sizes, int n_in,
                              void* d_out, int out_size) {
    const float* node_feats = (const float*)d_in[0];
    const float* edge_attr  = (const float*)d_in[1];
    const float* Wnp = (const float*)d_in[2];
    const float* bnp = (const float*)d_in[3];
    const float* Wep = (const float*)d_in[4];
    const float* bep = (const float*)d_in[5];
    const float* Wg1 = (const float*)d_in[6];
    const float* as1 = (const float*)d_in[7];
    const float* ad1 = (const float*)d_in[8];
    const float* bg1 = (const float*)d_in[9];
    const float* Wg2 = (const float*)d_in[10];
    const float* as2 = (const float*)d_in[11];
    const float* ad2 = (const float*)d_in[12];
    const float* bg2 = (const float*)d_in[13];
    const float* Wo  = (const float*)d_in[14];
    const float* bo  = (const float*)d_in[15];
    const int*   ei  = (const int*)d_in[16];
    float* out = (float*)d_out;

    float *px, *pxh, *px2, *pne, *pcnt;
    int* pdeg;
    cudaGetSymbolAddress((void**)&px,   g_x);
    cudaGetSymbolAddress((void**)&pxh,  g_xh);
    cudaGetSymbolAddress((void**)&px2,  g_x2);
    cudaGetSymbolAddress((void**)&pne,  g_ne);
    cudaGetSymbolAddress((void**)&pcnt, g_cnt);
    cudaGetSymbolAddress((void**)&pdeg, g_deg);

    dim3 gg(2, (NNODES + BM - 1) / BM);

    // 1. node projection -> g_x[:, 0:256]
    sgemm_bias<<<gg, 256>>>(node_feats, Wnp, bnp, px, NNODES, 256, 128, 128, 512, 0);

    // 2. edge aggregation (scatter mean) + edge projection -> g_x[:, 256:512]
    zero_kernel<<<((size_t)NNODES * 16 + 255) / 256, 256>>>(pne, (size_t)NNODES * 16);
    zero_kernel<<<(NNODES + 255) / 256, 256>>>(pcnt, NNODES);
    edge_mean_kernel<<<(NEDGES * 16 + 255) / 256, 256>>>(edge_attr, ei);
    nef_kernel<<<NNODES, 256>>>(Wep, bep);

    // 3. CSR build (shared by both GAT layers)
    zero_kernel<<<(NNODES + 255) / 256, 256>>>((float*)pdeg, NNODES);
    hist_kernel<<<(NAUG + 255) / 256, 256>>>(ei);
    scan_kernel<<<1, SCAN_T>>>();
    scatter_kernel<<<(NAUG + 255) / 256, 256>>>(ei);

    // 4. GAT layer 1: [N,512] -> [N,256] (+ELU)
    gat_layer(px, 512, Wg1, as1, ad1, bg1, pxh, px2);

    // 5. GAT layer 2: [N,256] -> [N,256] (+ELU)
    gat_layer(px2, 256, Wg2, as2, ad2, bg2, pxh, px2);

    // 6. output projection -> d_out
    sgemm_bias<<<gg, 256>>>(px2, Wo, bo, out, NNODES, 256, 256, 256, 256, 0);
}